// round 3
// baseline (speedup 1.0000x reference)
#include <cuda_runtime.h>
#include <cuda_bf16.h>

// out[m, r, t] = X0[r] + t * fl(dt * dXdt[r]),  m=0 -> S, m=1 -> I
// dSdt = -K *(L@S0) - beta*E0*S0 - gamma*I0*S0
// dIdt = -Ki*(L@I0) + 0.2*E0 - 0.01*I0
//
// Reference cumsum is jax associative_scan (log-depth, ~19 roundings/elem),
// so single-rounding fmaf((float)t, step, x0) matches to ~2e-6 relative.

#define NROWS 13

template <int VEC>
__global__ void __launch_bounds__(256)
sei_fill_kernel(const float* __restrict__ S0,
                const float* __restrict__ E0,
                const float* __restrict__ I0,
                const float* __restrict__ L,
                const float* __restrict__ beta_p,
                const float* __restrict__ gamma_p,
                const float* __restrict__ K_p,
                const float* __restrict__ Ki_p,
                const float* __restrict__ dt_p,
                float* __restrict__ out,
                int nt)
{
    const int y = blockIdx.y;          // y = m*13 + r
    const int m = y / NROWS;
    const int r = y - m * NROWS;

    __shared__ float s_step, s_x0;
    if (threadIdx.x == 0) {
        const float b  = *beta_p;
        const float g  = *gamma_p;
        const float K  = *K_p;
        const float Ki = *Ki_p;
        const float h  = *dt_p;
        float acc = 0.0f;
        if (m == 0) {
            #pragma unroll
            for (int c = 0; c < NROWS; ++c) acc = fmaf(L[r * NROWS + c], S0[c], acc);
            const float dS = -K * acc - b * E0[r] * S0[r] - g * I0[r] * S0[r];
            s_step = h * dS;
            s_x0   = S0[r];
        } else {
            #pragma unroll
            for (int c = 0; c < NROWS; ++c) acc = fmaf(L[r * NROWS + c], I0[c], acc);
            const float dI = -Ki * acc + 0.2f * E0[r] - 0.01f * I0[r];
            s_step = h * dI;
            s_x0   = I0[r];
        }
    }
    __syncthreads();

    const float step = s_step;
    const float x0   = s_x0;
    float* __restrict__ row = out + (long long)y * (long long)nt;

    if (VEC == 4) {
        // Each thread writes 4 float4s (16 elems), float4-coalesced within warp.
        // Per-block coverage: blockDim.x * 16 elements.
        const int elems_per_block = blockDim.x * 16;
        const int t_base = blockIdx.x * elems_per_block;
        #pragma unroll
        for (int j = 0; j < 4; ++j) {
            const int t0 = t_base + (j * blockDim.x + threadIdx.x) * 4;
            if (t0 + 3 < nt) {
                const float tf = (float)t0;
                float4 v;
                v.x = fmaf(tf,        step, x0);
                v.y = fmaf(tf + 1.0f, step, x0);
                v.z = fmaf(tf + 2.0f, step, x0);
                v.w = fmaf(tf + 3.0f, step, x0);
                *reinterpret_cast<float4*>(row + t0) = v;
            } else {
                for (int t = t0; t < nt; ++t)
                    row[t] = fmaf((float)t, step, x0);
            }
        }
    } else {
        // Scalar fallback (nt not divisible by 4 -> float4 rows would misalign)
        const int elems_per_block = blockDim.x * 16;
        const int t_base = blockIdx.x * elems_per_block;
        #pragma unroll
        for (int j = 0; j < 16; ++j) {
            const int t = t_base + j * blockDim.x + threadIdx.x;
            if (t < nt) row[t] = fmaf((float)t, step, x0);
        }
    }
}

extern "C" void kernel_launch(void* const* d_in, const int* in_sizes, int n_in,
                              void* d_out, int out_size)
{
    const float* S0   = (const float*)d_in[0];
    const float* E0   = (const float*)d_in[1];
    const float* I0   = (const float*)d_in[2];
    const float* L    = (const float*)d_in[3];
    const float* beta = (const float*)d_in[4];
    const float* gam  = (const float*)d_in[5];
    const float* K    = (const float*)d_in[6];
    const float* Ki   = (const float*)d_in[7];
    const float* dt   = (const float*)d_in[8];
    // d_in[9] is nt on device; recover nt on host from out_size = 2*13*nt.
    const int nt = out_size / (2 * NROWS);

    float* out = (float*)d_out;

    const int threads = 256;
    const int elems_per_block = threads * 16;
    dim3 grid((nt + elems_per_block - 1) / elems_per_block, 2 * NROWS, 1);
    dim3 block(threads, 1, 1);

    if ((nt & 3) == 0) {
        sei_fill_kernel<4><<<grid, block>>>(S0, E0, I0, L, beta, gam, K, Ki, dt, out, nt);
    } else {
        sei_fill_kernel<1><<<grid, block>>>(S0, E0, I0, L, beta, gam, K, Ki, dt, out, nt);
    }
}